// round 17
// baseline (speedup 1.0000x reference)
#include <cuda_runtime.h>

// Problem constants
#define TSEQ 1024
#define NB   32
#define ID   512
#define HD   512
#define GD   2048
#define NBLK_DIR 64
#define THREADS 384          // warps 0-7 rec, 8-11 producer team (blocks<128)
#define NTEAMS 188           // 128 + 20*3 producer teams
#define NTILES 65536         // 1024 t x 64 tiles (32 gates each)

typedef unsigned long long ull;

// Scratch (device globals)
__device__ float g_xw[(size_t)TSEQ * GD * NB];   // [t][g][b]
__device__ float g_hbuf[2][2][HD * NB];          // [dir][ping][u*32 + b]
__device__ unsigned g_barcnt[2];                 // monotonic h barriers
__device__ unsigned g_xw_done[TSEQ];             // monotonic per-t tile counters

// ---------------------------------------------------------------------------
__device__ __forceinline__ void ffma2(ull& d, ull a, ull b) {
    asm("fma.rn.f32x2 %0, %1, %2, %0;" : "+l"(d) : "l"(a), "l"(b));
}
__device__ __forceinline__ ull addf2(ull a, ull b) {
    ull r; asm("add.rn.f32x2 %0, %1, %2;" : "=l"(r) : "l"(a), "l"(b)); return r;
}
__device__ __forceinline__ ull dup2(float x) {
    ull r; asm("mov.b64 %0, {%1, %1};" : "=l"(r) : "f"(x)); return r;
}
__device__ __forceinline__ unsigned ld_acquire(const unsigned* p) {
    unsigned v; asm volatile("ld.acquire.gpu.u32 %0, [%1];" : "=r"(v) : "l"(p) : "memory");
    return v;
}
__device__ __forceinline__ void red_release(unsigned* p) {
    asm volatile("red.release.gpu.global.add.u32 [%0], %1;" :: "l"(p), "r"(1u) : "memory");
}
__device__ __forceinline__ float sigf(float x) {
    return __fdividef(1.f, 1.f + __expf(-x));
}
__device__ __forceinline__ float tanhfast(float x) {
    return __fdividef(2.f, 1.f + __expf(-2.f * x)) - 1.f;
}
#define BAR_REC()   asm volatile("bar.sync 1, 256;" ::: "memory")
#define BAR_TEAM(i) asm volatile("bar.sync %0, 128;" :: "r"(i) : "memory")

// smem float offsets
#define REC_FLOATS (16384 + 16384 + 8 * 1088)   // 41472 floats (R13 rec layout)
#define TEAM_FLOATS 3456                        // ws2 1152 ull (2304 f) + xs 1152 f
#define TOTAL_SMEM_B ((REC_FLOATS + 3 * TEAM_FLOATS) * 4)   // 207360

// ---------------------------------------------------------------------------
// Producer team body: computes tiles (t, 32 gates) of xw = x@Wih^T + biases,
// zeroes its d_out slice, signals g_xw_done[t]. 4 warps, 128 threads.
// ---------------------------------------------------------------------------
__device__ void xw_team(
    const float* __restrict__ x, const float* __restrict__ Wih,
    const float* __restrict__ bih, const float* __restrict__ bhh,
    float4* __restrict__ out4, float* tbuf, int team, int bar_id, int tg_tid)
{
    ull*   ws2 = (ull*)tbuf;        // [kk][gate], ull stride 36 -> [36*kk + g]
    float* xs  = tbuf + 2304;       // [kk][b], float stride 36

    int w2   = tg_tid >> 5;
    int lane = tg_tid & 31;
    int ks   = lane >> 3;
    int bq   = lane & 7;
    int gb   = ((ks & 1) << 2) | (ks & 2);   // final gate pair after fold
    bool kA  = (lane & 8) != 0;
    bool kB  = (lane & 16) != 0;

    for (int idx = team; idx < NTILES; idx += NTEAMS) {
        int t_order = idx >> 6;
        int gg = idx & 63;
        int t  = (t_order & 1) ? (TSEQ - 1 - (t_order >> 1)) : (t_order >> 1);
        int g0t = gg << 5;

        // zero this tile's d_out slice (one batch-row of t)
        if (tg_tid < 64)
            out4[(size_t)t * 4096 + gg * 64 + tg_tid] = make_float4(0.f, 0.f, 0.f, 0.f);

        float bias0 = bih[g0t + 8 * w2 + gb]     + bhh[g0t + 8 * w2 + gb];
        float bias1 = bih[g0t + 8 * w2 + gb + 1] + bhh[g0t + 8 * w2 + gb + 1];

        ull acc[8][2];
#pragma unroll
        for (int i = 0; i < 8; i++) { acc[i][0] = 0ull; acc[i][1] = 0ull; }

        const float* xt = x + (size_t)t * NB * ID;

        for (int kc = 0; kc < ID; kc += 32) {
            BAR_TEAM(bar_id);    // previous GEMV reads done
            // stage W k-octet 8*w2 for all 32 gates (lane = gate) as dup'd pairs
            {
                const float* wsrc = Wih + (size_t)(g0t + lane) * ID + kc + (w2 << 3);
                float4 a = *(const float4*)wsrc;
                float4 b = *(const float4*)(wsrc + 4);
                ull* wp = ws2 + (w2 << 3) * 36 + lane;
                wp[0 * 36] = dup2(a.x); wp[1 * 36] = dup2(a.y);
                wp[2 * 36] = dup2(a.z); wp[3 * 36] = dup2(a.w);
                wp[4 * 36] = dup2(b.x); wp[5 * 36] = dup2(b.y);
                wp[6 * 36] = dup2(b.z); wp[7 * 36] = dup2(b.w);
            }
            // stage x k-octet 8*w2 for all 32 batches (lane = b)
            {
                const float* xsrc = xt + (size_t)lane * ID + kc + (w2 << 3);
                float4 a = *(const float4*)xsrc;
                float4 b = *(const float4*)(xsrc + 4);
                float* xp = xs + (w2 << 3) * 36 + lane;
                xp[0 * 36] = a.x; xp[1 * 36] = a.y; xp[2 * 36] = a.z; xp[3 * 36] = a.w;
                xp[4 * 36] = b.x; xp[5 * 36] = b.y; xp[6 * 36] = b.z; xp[7 * 36] = b.w;
            }
            BAR_TEAM(bar_id);

            // GEMV: 8 iters, k = 4*it + ks; warp w2 -> gates 8w2..+7
#pragma unroll
            for (int it = 0; it < 8; it++) {
                int kk = (it << 2) | ks;
                const ull* wrow = ws2 + kk * 36 + (w2 << 3);
                ulonglong2 w01 = *(const ulonglong2*)(wrow);
                ulonglong2 w23 = *(const ulonglong2*)(wrow + 2);
                ulonglong2 w45 = *(const ulonglong2*)(wrow + 4);
                ulonglong2 w67 = *(const ulonglong2*)(wrow + 6);
                ulonglong2 xv = *(const ulonglong2*)(xs + kk * 36 + (bq << 2));
                ffma2(acc[0][0], w01.x, xv.x); ffma2(acc[0][1], w01.x, xv.y);
                ffma2(acc[1][0], w01.y, xv.x); ffma2(acc[1][1], w01.y, xv.y);
                ffma2(acc[2][0], w23.x, xv.x); ffma2(acc[2][1], w23.x, xv.y);
                ffma2(acc[3][0], w23.y, xv.x); ffma2(acc[3][1], w23.y, xv.y);
                ffma2(acc[4][0], w45.x, xv.x); ffma2(acc[4][1], w45.x, xv.y);
                ffma2(acc[5][0], w45.y, xv.x); ffma2(acc[5][1], w45.y, xv.y);
                ffma2(acc[6][0], w67.x, xv.x); ffma2(acc[6][1], w67.x, xv.y);
                ffma2(acc[7][0], w67.y, xv.x); ffma2(acc[7][1], w67.y, xv.y);
            }
        }

        // 2-round k-fold (static register indices only)
        ull kept[4][2];
#pragma unroll
        for (int j = 0; j < 4; j++)
#pragma unroll
            for (int p = 0; p < 2; p++) {
                ull snd = kA ? acc[j][p] : acc[j + 4][p];
                ull rcv = __shfl_xor_sync(0xFFFFFFFFu, snd, 8);
                kept[j][p] = addf2(kA ? acc[j + 4][p] : acc[j][p], rcv);
            }
        ull fin[2][2];
#pragma unroll
        for (int j = 0; j < 2; j++)
#pragma unroll
            for (int p = 0; p < 2; p++) {
                ull snd = kB ? kept[j][p] : kept[j + 2][p];
                ull rcv = __shfl_xor_sync(0xFFFFFFFFu, snd, 16);
                fin[j][p] = addf2(kB ? kept[j + 2][p] : kept[j][p], rcv);
            }
        {
            ull b0 = dup2(bias0), b1 = dup2(bias1);
            float* outp = g_xw + ((size_t)t * GD + g0t + 8 * w2 + gb) * NB + 4 * bq;
            *(ull*)(outp)          = addf2(fin[0][0], b0);
            *(ull*)(outp + 2)      = addf2(fin[0][1], b0);
            *(ull*)(outp + NB)     = addf2(fin[1][0], b1);
            *(ull*)(outp + NB + 2) = addf2(fin[1][1], b1);
        }

        // publish: all team stores done -> one release arrive on this t
        BAR_TEAM(bar_id);
        if (tg_tid == 0) red_release(&g_xw_done[t]);
    }
}

// ---------------------------------------------------------------------------
// Fused kernel: blocks 0..127 = rec (warps 0-7) + 1 producer team (warps 8-11);
// blocks 128..147 = 3 producer teams.
// ---------------------------------------------------------------------------
__global__ __launch_bounds__(THREADS, 1) void lstm_fused(
    const float* __restrict__ x,
    const float* __restrict__ Wih,
    const float* __restrict__ Whh,
    const float* __restrict__ bih,
    const float* __restrict__ bhh,
    float* __restrict__ out)
{
    extern __shared__ float smem[];
    int bid  = blockIdx.x;
    int tid  = threadIdx.x;
    int w    = tid >> 5;

    // ---- producer teams ----
    if (bid >= 128 || w >= 8) {
        int team_local = (bid < 128) ? 0 : (w >> 2);
        int team   = (bid < 128) ? bid : 128 + (bid - 128) * 3 + (w >> 2);
        int bar_id = 2 + team_local;
        int tg_tid = tid & 127;
        float* tbuf = smem + REC_FLOATS + team_local * TEAM_FLOATS;
        xw_team(x, Wih, bih, bhh, (float4*)out, tbuf, team, bar_id, tg_tid);
        return;
    }

    // ---- recurrence (R13 verbatim, + xw_done wait; named barrier 1) ----
    float* Wt   = smem;             // 64KB: Wt[k*32 + row]
    float* Hs   = smem + 16384;     // 64KB: Hs[u*32 + b]
    float* gbuf = smem + 32768;     // 34KB

    int dir  = bid >> 6;
    int j0   = (bid & 63) << 3;
    int lane = tid & 31;
    int ks0  = lane >> 4;
    int rg   = (lane >> 2) & 3;
    int bg   = lane & 3;
    int u_l  = w;
    int gu   = j0 + u_l;

#pragma unroll 4
    for (int i = 0; i < 64; i++) {
        int idx = tid + (i << 8);
        int row = idx >> 9;
        int k   = idx & 511;
        int gr  = ((row >> 3) << 9) + j0 + (row & 7);
        Wt[k * 32 + row] = Whh[(size_t)gr * HD + k];
    }

    float c_reg = 0.f, h_reg = 0.f;
    g_hbuf[dir][0][gu * 32 + lane] = 0.f;

    // monotonic bases (replay-safe): h barrier + xw epoch
    unsigned base = ld_acquire(&g_barcnt[dir]) & ~(unsigned)(NBLK_DIR - 1);
    unsigned xw_target = (base / (unsigned)(NBLK_DIR * (TSEQ + 1))) * 64u + 64u;

    BAR_REC();
    if (tid == 0) red_release(&g_barcnt[dir]);   // publish h0

    const float4* W4 = (const float4*)Wt;
    const float4* H4 = (const float4*)Hs;
    const int kbeg = (w << 6) + (ks0 << 5);

    for (int s = 0; s < TSEQ; s++) {
        int t = dir ? (TSEQ - 1 - s) : s;
        const float* xw_t = g_xw + (size_t)t * GD * NB;

        // wait: xw[t] produced AND all blocks' h_s published
        if (tid == 0) {
            while ((int)(ld_acquire(&g_xw_done[t]) - xw_target) < 0) { }
            unsigned htgt = base + (unsigned)NBLK_DIR * (s + 1);
            while ((int)(ld_acquire(&g_barcnt[dir]) - htgt) < 0) { }
        }
        BAR_REC();

        // xw gate inputs (freshly produced -> L2; bypass L1 for coherence)
        float xg0 = __ldcg(&xw_t[(0 * HD + gu) * NB + lane]);
        float xg1 = __ldcg(&xw_t[(1 * HD + gu) * NB + lane]);
        float xg2 = __ldcg(&xw_t[(2 * HD + gu) * NB + lane]);
        float xg3 = __ldcg(&xw_t[(3 * HD + gu) * NB + lane]);

        // per-warp copy of own h k-range [64w, 64w+64)
        {
            const float4* hsrc = (const float4*)g_hbuf[dir][s & 1];
            float4* hdst = (float4*)Hs;
#pragma unroll
            for (int i = 0; i < 16; i++) {
                int idx = (w << 9) + (i << 5) + lane;
                hdst[idx] = __ldcg(&hsrc[idx]);
            }
            __syncwarp();
        }

        // GEMV: 8 rows x 4 batch-pairs per lane over 32 k
        ull acc[8][4];
#pragma unroll
        for (int i = 0; i < 8; i++)
#pragma unroll
            for (int j = 0; j < 4; j++) acc[i][j] = 0ull;

#pragma unroll 4
        for (int kk = 0; kk < 32; kk++) {
            int k = kbeg + kk;
            float4 wA = W4[(k << 3) + (rg << 1)];
            float4 wB = W4[(k << 3) + (rg << 1) + 1];
            ulonglong2 hA = *(const ulonglong2*)&H4[(k << 3) + (bg << 1)];
            ulonglong2 hB = *(const ulonglong2*)&H4[(k << 3) + (bg << 1) + 1];
            float wf[8] = {wA.x, wA.y, wA.z, wA.w, wB.x, wB.y, wB.z, wB.w};
#pragma unroll
            for (int i = 0; i < 8; i++) {
                ull wd = dup2(wf[i]);
                ffma2(acc[i][0], wd, hA.x);
                ffma2(acc[i][1], wd, hA.y);
                ffma2(acc[i][2], wd, hB.x);
                ffma2(acc[i][3], wd, hB.y);
            }
        }

        // fold k-halves + store (static register indices only)
        {
            float* gp0 = gbuf + w * 1088 + (bg << 3) + (ks0 << 2);
#pragma unroll
            for (int i = 0; i < 8; i++) {
                ull s0 = ks0 ? acc[i][0] : acc[i][2];
                ull s1 = ks0 ? acc[i][1] : acc[i][3];
                ull r0 = __shfl_xor_sync(0xFFFFFFFFu, s0, 16);
                ull r1 = __shfl_xor_sync(0xFFFFFFFFu, s1, 16);
                ull k0 = ks0 ? acc[i][2] : acc[i][0];
                ull k1 = ks0 ? acc[i][3] : acc[i][1];
                ull v0 = addf2(k0, r0);
                ull v1 = addf2(k1, r1);
                float* gp = gp0 + ((rg << 3) + i) * 34;
                *(ull*)gp = v0;
                *(ull*)(gp + 2) = v1;
            }
        }
        BAR_REC();

        // cell update
        {
            int b = lane;
            float iv = xg0, fv = xg1, gv = xg2, ov = xg3;
#pragma unroll
            for (int sw = 0; sw < 8; sw++) {
                const float* gp = gbuf + sw * 1088 + b;
                iv += gp[(0 * 8 + u_l) * 34];
                fv += gp[(1 * 8 + u_l) * 34];
                gv += gp[(2 * 8 + u_l) * 34];
                ov += gp[(3 * 8 + u_l) * 34];
            }
            iv = sigf(iv);
            fv = sigf(fv);
            gv = tanhfast(gv);
            ov = sigf(ov);
            float c_new = fv * c_reg + iv * gv;
            float h_new = ov * tanhfast(c_new);
            c_reg = 0.9f * c_new + 0.1f * c_reg;
            float h_bl = 0.9f * h_new + 0.1f * h_reg;
            h_reg = h_bl;
            g_hbuf[dir][(s + 1) & 1][gu * 32 + lane] = h_bl;
            // exactly two commutative fp32 adds per output element (zeroed by
            // the producer of tile t before g_xw_done[t] release) -> deterministic
            atomicAdd(&out[(size_t)t * (NB * HD) + lane * HD + gu], h_bl);
        }

        BAR_REC();
        if (tid == 0) red_release(&g_barcnt[dir]);
    }
}

// ---------------------------------------------------------------------------
extern "C" void kernel_launch(void* const* d_in, const int* in_sizes, int n_in,
                              void* d_out, int out_size) {
    const float* x   = (const float*)d_in[0];
    const float* Wih = (const float*)d_in[1];
    const float* Whh = (const float*)d_in[2];
    const float* bih = (const float*)d_in[3];
    const float* bhh = (const float*)d_in[4];
    float* out = (float*)d_out;

    cudaFuncSetAttribute(lstm_fused, cudaFuncAttributeMaxDynamicSharedMemorySize,
                         TOTAL_SMEM_B);
    lstm_fused<<<148, THREADS, TOTAL_SMEM_B>>>(x, Wih, Whh, bih, bhh, out);
}